// round 10
// baseline (speedup 1.0000x reference)
#include <cuda_runtime.h>
#include <cuda_bf16.h>
#include <cstdint>

// Problem shapes (fixed by setup_inputs)
#define M_DIM 4096
#define K_DIM 2048
#define N_DIM 4096

// Detect tcgen05 availability per compilation pass (compute_103a yes, compute_103 no)
#define HAS_TCGEN05 0
#ifdef __CUDA_ARCH__
#ifdef __CUDA_ARCH_HAS_FEATURE__
#if __CUDA_ARCH_HAS_FEATURE__(SM103_ALL) || __CUDA_ARCH_HAS_FEATURE__(SM100_ALL)
#undef HAS_TCGEN05
#define HAS_TCGEN05 1
#endif
#endif
#endif

// ---------------- device scratch (no allocation allowed) ----------------
__device__ __nv_bfloat16 g_qA[(size_t)M_DIM * K_DIM];   // centered quantized A (bf16), [M,K] K-major
__device__ __nv_bfloat16 g_qB[(size_t)N_DIM * K_DIM];   // centered quantized B^T (bf16), [N,K] K-major

#define MMG 1024
__device__ float g_pminA[MMG], g_pmaxA[MMG], g_pminB[MMG], g_pmaxB[MMG];
__device__ float g_scaleA, g_zeroA, g_scaleB, g_zeroB, g_sAB;

// ---------------- generic helpers (valid on all targets) ----------------
__device__ __forceinline__ uint32_t smem_u32(const void* p) {
    return (uint32_t)__cvta_generic_to_shared(p);
}
__device__ __forceinline__ void cp_async16(uint32_t dst, const void* src) {
    asm volatile("cp.async.cg.shared.global [%0], [%1], 16;\n" :: "r"(dst), "l"(src) : "memory");
}
__device__ __forceinline__ void cp_commit() {
    asm volatile("cp.async.commit_group;\n" ::: "memory");
}
template <int N>
__device__ __forceinline__ void cp_wait() {
    asm volatile("cp.async.wait_group %0;\n" :: "n"(N) : "memory");
}
__device__ __forceinline__ void ldsm_x4(uint32_t* r, uint32_t addr) {
    asm volatile("ldmatrix.sync.aligned.m8n8.x4.shared.b16 {%0,%1,%2,%3}, [%4];\n"
                 : "=r"(r[0]), "=r"(r[1]), "=r"(r[2]), "=r"(r[3]) : "r"(addr));
}
__device__ __forceinline__ void mma_bf16(float* d, const uint32_t* a, const uint32_t* b) {
    asm volatile("mma.sync.aligned.m16n8k16.row.col.f32.bf16.bf16.f32 "
                 "{%0,%1,%2,%3}, {%4,%5,%6,%7}, {%8,%9}, {%0,%1,%2,%3};\n"
                 : "+f"(d[0]), "+f"(d[1]), "+f"(d[2]), "+f"(d[3])
                 : "r"(a[0]), "r"(a[1]), "r"(a[2]), "r"(a[3]),
                   "r"(b[0]), "r"(b[1]));
}

#define SMEM_SWIZZLE_128B(byte_offset) ((byte_offset) ^ (((byte_offset) >> 3) & 0x70))

// ---------------- tcgen05-only helpers ----------------
#if HAS_TCGEN05
__device__ __forceinline__ uint32_t elect_one_pred() {
    uint32_t pred;
    asm volatile("{\n\t.reg .pred p;\n\telect.sync _|p, 0xFFFFFFFF;\n\tselp.b32 %0, 1, 0, p;\n\t}"
                 : "=r"(pred));
    return pred;
}
__device__ __forceinline__ uint32_t cluster_rank() {
    uint32_t r;
    asm("mov.u32 %0, %%cluster_ctarank;" : "=r"(r));
    return r;
}

// SW128 K-major SMEM descriptor (Blackwell): layout=SW128, version=1, SBO=64, LBO=1
static constexpr uint64_t SMEM_DESC_BASE_SW128 =
    (uint64_t(2) << 61) | (uint64_t(1) << 46) | (uint64_t(64) << 32) | (uint64_t(1) << 16);
#define MAKE_SMEM_DESC(base_addr) \
    (SMEM_DESC_BASE_SW128 | ((uint64_t)((base_addr) >> 4) & 0x3FFF))

#define MBARRIER_INIT(mbar, count) \
    asm volatile("mbarrier.init.shared.b64 [%0], %1;" :: "r"((uint32_t)(mbar)), "r"((uint32_t)(count)) : "memory")
#define MBARRIER_INVAL(mbar) \
    asm volatile("mbarrier.inval.shared.b64 [%0];" :: "r"((uint32_t)(mbar)) : "memory")
// Arrive on rank-0 CTA's barrier at the same SMEM offset (cluster-scope release).
#define MBARRIER_ARRIVE_RANK0(mbar) \
    asm volatile("{\n\t.reg .b32 ra;\n\tmapa.shared::cluster.u32 ra, %0, 0;\n\t" \
        "mbarrier.arrive.release.cluster.shared::cluster.b64 _, [ra];\n\t}" \
        :: "r"((uint32_t)(mbar)) : "memory")
#define MBARRIER_WAIT_PARITY(mbar, parity) do { \
    uint32_t _mbar = (uint32_t)(mbar); \
    uint32_t _par = (uint32_t)(parity); \
    uint32_t _done; \
    asm volatile("{\n\t.reg .pred p;\n\t" \
        "mbarrier.try_wait.parity.acquire.cta.shared::cta.b64 p, [%1], %2;\n\t" \
        "selp.b32 %0, 1, 0, p;\n\t}" : "=r"(_done) : "r"(_mbar), "r"(_par) : "memory"); \
    if (!_done) { \
        asm volatile("{\n\t.reg .pred P1;\n\t" \
            "WAIT_LOOP_%=:\n\t" \
            "mbarrier.try_wait.parity.acquire.cta.shared::cta.b64 P1, [%0], %1, 0x989680;\n\t" \
            "@P1 bra.uni WAIT_DONE_%=;\n\t" \
            "bra.uni WAIT_LOOP_%=;\n\t" \
            "WAIT_DONE_%=:\n\t}" :: "r"(_mbar), "r"(_par) : "memory"); \
    } \
} while (0)
// Cluster-scope acquire wait (for barriers receiving remote arrivals)
#define MBARRIER_WAIT_PARITY_CLU(mbar, parity) do { \
    uint32_t _mbar = (uint32_t)(mbar); \
    uint32_t _par = (uint32_t)(parity); \
    uint32_t _done; \
    asm volatile("{\n\t.reg .pred p;\n\t" \
        "mbarrier.try_wait.parity.acquire.cluster.shared::cta.b64 p, [%1], %2;\n\t" \
        "selp.b32 %0, 1, 0, p;\n\t}" : "=r"(_done) : "r"(_mbar), "r"(_par) : "memory"); \
    if (!_done) { \
        asm volatile("{\n\t.reg .pred P1;\n\t" \
            "WAIT_LOOP_%=:\n\t" \
            "mbarrier.try_wait.parity.acquire.cluster.shared::cta.b64 P1, [%0], %1, 0x989680;\n\t" \
            "@P1 bra.uni WAIT_DONE_%=;\n\t" \
            "bra.uni WAIT_LOOP_%=;\n\t" \
            "WAIT_DONE_%=:\n\t}" :: "r"(_mbar), "r"(_par) : "memory"); \
    } \
} while (0)

#define FENCE_PROXY_ASYNC() \
    asm volatile("fence.proxy.async.shared::cta;" ::: "memory")
#define TCGEN05_FENCE_AFTER() \
    asm volatile("tcgen05.fence::after_thread_sync;" ::: "memory")
#define TCGEN05_FENCE_BEFORE() \
    asm volatile("tcgen05.fence::before_thread_sync;" ::: "memory")
#define TCGEN05_ALLOC_CG2(smem_addr, nCols) \
    asm volatile("tcgen05.alloc.cta_group::2.sync.aligned.shared::cta.b32 [%0], %1;" \
                 :: "r"((uint32_t)(smem_addr)), "r"((uint32_t)(nCols)) : "memory")
#define TCGEN05_DEALLOC_CG2(tmem, nCols) \
    asm volatile("tcgen05.dealloc.cta_group::2.sync.aligned.b32 %0, %1;" :: "r"(tmem), "r"((uint32_t)(nCols)))
#define TCGEN05_RELINQUISH_CG2() \
    asm volatile("tcgen05.relinquish_alloc_permit.cta_group::2.sync.aligned;")
#define TCGEN05_COMMIT_MC_CG2(mbar, mask) \
    asm volatile("tcgen05.commit.cta_group::2.mbarrier::arrive::one.shared::cluster.multicast::cluster.b64 [%0], %1;" \
                 :: "r"((uint32_t)(mbar)), "h"((uint16_t)(mask)) : "memory")
#define TCGEN05_WAIT_LD() \
    asm volatile("tcgen05.wait::ld.sync.aligned;" ::: "memory")
#define CLUSTER_SYNC() do { \
    asm volatile("barrier.cluster.arrive.aligned;" ::: "memory"); \
    asm volatile("barrier.cluster.wait.aligned;" ::: "memory"); \
} while (0)

#define TCGEN05_LD_32X32B_X32(r, tmem_addr) \
    asm volatile("tcgen05.ld.sync.aligned.32x32b.x32.b32 " \
        "{%0, %1, %2, %3, %4, %5, %6, %7, %8, %9, %10, %11, %12, %13, %14, %15, " \
        "%16, %17, %18, %19, %20, %21, %22, %23, %24, %25, %26, %27, %28, %29, %30, %31}, [%32];" \
        : "=r"((r)[0]), "=r"((r)[1]), "=r"((r)[2]), "=r"((r)[3]), \
          "=r"((r)[4]), "=r"((r)[5]), "=r"((r)[6]), "=r"((r)[7]), \
          "=r"((r)[8]), "=r"((r)[9]), "=r"((r)[10]), "=r"((r)[11]), \
          "=r"((r)[12]), "=r"((r)[13]), "=r"((r)[14]), "=r"((r)[15]), \
          "=r"((r)[16]), "=r"((r)[17]), "=r"((r)[18]), "=r"((r)[19]), \
          "=r"((r)[20]), "=r"((r)[21]), "=r"((r)[22]), "=r"((r)[23]), \
          "=r"((r)[24]), "=r"((r)[25]), "=r"((r)[26]), "=r"((r)[27]), \
          "=r"((r)[28]), "=r"((r)[29]), "=r"((r)[30]), "=r"((r)[31]) \
        : "r"(tmem_addr))

// cg2 bf16 SS MMA (8-zero disable-lane list, per test_2cta_mma_bf16)
__device__ __forceinline__ void mma_f16_ss_cg2(uint32_t d_tmem, uint64_t a_desc, uint64_t b_desc,
                                               uint32_t idesc, uint32_t enable_d) {
    asm volatile(
        "{\n\t.reg .pred p;\n\t"
        "setp.ne.u32 p, %4, 0;\n\t"
        "tcgen05.mma.cta_group::2.kind::f16 [%0], %1, %2, %3, {%5, %5, %5, %5, %5, %5, %5, %5}, p;\n\t}"
        :: "r"(d_tmem), "l"(a_desc), "l"(b_desc), "r"(idesc), "r"(enable_d), "r"(0u)
        : "memory");
}
#endif  // HAS_TCGEN05

// ---------------- 1) fused per-tensor min/max partials (A and B in one launch) ----------------
__global__ void minmax_fused(const float* __restrict__ A, const float* __restrict__ B) {
    const int which = (blockIdx.x >= MMG) ? 1 : 0;
    const int blk = which ? (blockIdx.x - MMG) : blockIdx.x;
    const float* __restrict__ x = which ? B : A;
    const int n4 = (which ? (K_DIM * N_DIM) : (M_DIM * K_DIM)) >> 2;

    float vmin = 3.4028235e38f, vmax = -3.4028235e38f;
    int idx = blk * blockDim.x + threadIdx.x;
    int stride = MMG * blockDim.x;
    const float4* x4 = (const float4*)x;
    for (int i = idx; i < n4; i += stride) {
        float4 v = x4[i];
        vmin = fminf(vmin, fminf(fminf(v.x, v.y), fminf(v.z, v.w)));
        vmax = fmaxf(vmax, fmaxf(fmaxf(v.x, v.y), fmaxf(v.z, v.w)));
    }
    #pragma unroll
    for (int o = 16; o > 0; o >>= 1) {
        vmin = fminf(vmin, __shfl_xor_sync(0xffffffffu, vmin, o));
        vmax = fmaxf(vmax, __shfl_xor_sync(0xffffffffu, vmax, o));
    }
    __shared__ float smin[8], smax[8];
    int warp = threadIdx.x >> 5, lane = threadIdx.x & 31;
    if (lane == 0) { smin[warp] = vmin; smax[warp] = vmax; }
    __syncthreads();
    if (threadIdx.x == 0) {
        float m0 = smin[0], m1 = smax[0];
        #pragma unroll
        for (int w = 1; w < 8; w++) { m0 = fminf(m0, smin[w]); m1 = fmaxf(m1, smax[w]); }
        if (which) { g_pminB[blk] = m0; g_pmaxB[blk] = m1; }
        else       { g_pminA[blk] = m0; g_pmaxA[blk] = m1; }
    }
}

// ---------------- 2) finalize scales/zeros ----------------
__global__ void finalize_scales() {
    __shared__ float s0[256], s1[256], s2[256], s3[256];
    int t = threadIdx.x;
    float mnA = 3.4028235e38f, mxA = -3.4028235e38f;
    float mnB = 3.4028235e38f, mxB = -3.4028235e38f;
    for (int i = t; i < MMG; i += 256) {
        mnA = fminf(mnA, g_pminA[i]); mxA = fmaxf(mxA, g_pmaxA[i]);
        mnB = fminf(mnB, g_pminB[i]); mxB = fmaxf(mxB, g_pmaxB[i]);
    }
    s0[t] = mnA; s1[t] = mxA; s2[t] = mnB; s3[t] = mxB;
    __syncthreads();
    for (int o = 128; o > 0; o >>= 1) {
        if (t < o) {
            s0[t] = fminf(s0[t], s0[t + o]);
            s1[t] = fmaxf(s1[t], s1[t + o]);
            s2[t] = fminf(s2[t], s2[t + o]);
            s3[t] = fmaxf(s3[t], s3[t + o]);
        }
        __syncthreads();
    }
    if (t == 0) {
        float sA = __fdiv_rn(s1[0] - s0[0], 255.0f);
        float zA = rintf(__fdiv_rn(-s0[0], sA));
        float sB = __fdiv_rn(s3[0] - s2[0], 255.0f);
        float zB = rintf(__fdiv_rn(-s2[0], sB));
        g_scaleA = sA; g_zeroA = zA;
        g_scaleB = sB; g_zeroB = zB;
        g_sAB = sA * sB;
    }
}

// ---------------- 3a) quantize A (centered, bf16) ----------------
__global__ void quantize_A(const float* __restrict__ x, int n4) {
    int i = blockIdx.x * blockDim.x + threadIdx.x;
    if (i >= n4) return;
    float s = g_scaleA, z = g_zeroA;
    float4 v = ((const float4*)x)[i];
    float q0 = fminf(fmaxf(rintf(__fdiv_rn(v.x, s)) + z, 0.0f), 255.0f) - z;
    float q1 = fminf(fmaxf(rintf(__fdiv_rn(v.y, s)) + z, 0.0f), 255.0f) - z;
    float q2 = fminf(fmaxf(rintf(__fdiv_rn(v.z, s)) + z, 0.0f), 255.0f) - z;
    float q3 = fminf(fmaxf(rintf(__fdiv_rn(v.w, s)) + z, 0.0f), 255.0f) - z;
    __nv_bfloat162 p0 = make_bfloat162(__float2bfloat16_rn(q0), __float2bfloat16_rn(q1));
    __nv_bfloat162 p1 = make_bfloat162(__float2bfloat16_rn(q2), __float2bfloat16_rn(q3));
    uint32_t u0, u1;
    memcpy(&u0, &p0, 4); memcpy(&u1, &p1, 4);
    ((uint2*)g_qA)[i] = make_uint2(u0, u1);
}

// ---------------- 3b) quantize B fused with transpose: g_qB[n*K + k] ----------------
__global__ void quantize_B_T(const float* __restrict__ B) {
    __shared__ float tile[32][33];
    int n0 = blockIdx.x * 32, k0 = blockIdx.y * 32;
    int tx = threadIdx.x, ty = threadIdx.y;
    #pragma unroll
    for (int j = 0; j < 4; j++)
        tile[ty + 8 * j][tx] = B[(size_t)(k0 + ty + 8 * j) * N_DIM + n0 + tx];
    __syncthreads();
    float s = g_scaleB, z = g_zeroB;
    #pragma unroll
    for (int j = 0; j < 4; j++) {
        int nn = ty + 8 * j;   // local n
        int kk = tx;           // local k
        float v = tile[kk][nn];
        float q = fminf(fmaxf(rintf(__fdiv_rn(v, s)) + z, 0.0f), 255.0f) - z;
        g_qB[(size_t)(n0 + nn) * K_DIM + k0 + kk] = __float2bfloat16_rn(q);
    }
}

// ---------------- 4) GEMM: 2CTA cg2 tcgen05 on sm_103a, mma.sync fallback on plain sm_103 ----------------
#define STAGES 4
#define TILE_M 256         // per cluster pair
#define BN 256
#define BK 64
#define KT (K_DIM / BK)    // 32
// idesc (kind::f16): dtype=F32(bit4), atype=BF16(bit7), btype=BF16(bit10), N/8<<17, M/16<<24 (M=256)
#define GEMM_IDESC ((1u << 4) | (1u << 7) | (1u << 10) | ((BN / 8) << 17) | ((TILE_M / 16) << 24))

// dynamic SMEM layout (tcgen05 path) — per CTA
#define SM_TPTR_OFF   0
#define SM_FULL_OFF   16                           // leader's full[4] (count 256, remote arrivals)
#define SM_EMPTY_OFF  48                           // per-CTA empty[4] (count 1, commit multicast)
#define SM_DONE_OFF   80
#define SM_A_OFF(s)   (1024 + (s) * 16384)         // 128 rows x 128B per stage
#define SM_B_OFF(s)   (66560 + (s) * 16384)        // 128 rows x 128B per stage (N/2 split)
#define SMEM_TOTAL    132608

__global__ void __launch_bounds__(256, 1) __cluster_dims__(2, 1, 1)
gemm_tc(float* __restrict__ C) {
    extern __shared__ char smem[];
    const int tid = threadIdx.x, wid = tid >> 5, lane = tid & 31;

#if HAS_TCGEN05
    // ================= 2CTA cg2 tcgen05 path (sm_103a) =================
    const uint32_t sb = smem_u32(smem);
    const uint32_t rank = cluster_rank();
    const int tileM = blockIdx.y;
    const int bn = (blockIdx.x >> 1) * BN;
    const int bm_cta = tileM * TILE_M + (int)rank * 128;   // this CTA's 128 A-rows / D-rows

    if (tid == 0) {
        #pragma unroll
        for (int s = 0; s < STAGES; s++) {
            MBARRIER_INIT(sb + SM_FULL_OFF + 8 * s, 256);  // 128 producers x 2 CTAs
            MBARRIER_INIT(sb + SM_EMPTY_OFF + 8 * s, 1);   // commit multicast arrival
        }
        MBARRIER_INIT(sb + SM_DONE_OFF, 1);
    }
    if (wid == 4) TCGEN05_ALLOC_CG2(sb + SM_TPTR_OFF, 256);
    __syncthreads();
    // All barriers (both CTAs) must be live before any remote arrive / multicast commit.
    CLUSTER_SYNC();

    uint32_t tmem;
    asm volatile("ld.shared.b32 %0, [%1];" : "=r"(tmem) : "r"(sb + SM_TPTR_OFF));

    if (wid == 4) {
        // ---- MMA warp (leader CTA only issues) ----
        TCGEN05_FENCE_AFTER();
        if (rank == 0) {
            int ph = 0;
            for (int kt = 0; kt < KT; kt++) {
                const int s = kt & 3;
                MBARRIER_WAIT_PARITY_CLU(sb + SM_FULL_OFF + 8 * s, ph);
                if (s == 3) ph ^= 1;
                if (elect_one_pred()) {
                    const uint64_t ad = MAKE_SMEM_DESC(sb + SM_A_OFF(s));
                    const uint64_t bd = MAKE_SMEM_DESC(sb + SM_B_OFF(s));
                    #pragma unroll
                    for (int ks = 0; ks < 4; ks++) {
                        uint32_t en = (kt > 0 || ks > 0) ? 1u : 0u;
                        mma_f16_ss_cg2(tmem, ad + ks * 2, bd + ks * 2, GEMM_IDESC, en);
                    }
                    TCGEN05_COMMIT_MC_CG2(sb + SM_EMPTY_OFF + 8 * s, 0x3);
                }
            }
            if (elect_one_pred()) TCGEN05_COMMIT_MC_CG2(sb + SM_DONE_OFF, 0x3);
        }
    } else if (wid < 4) {
        // ---- producer warps 0-3 (128 threads per CTA) ----
        const __nv_bfloat16* __restrict__ Aq = g_qA;
        const __nv_bfloat16* __restrict__ Bq = g_qB;
        const int bn_cta = bn + (int)rank * 128;   // this CTA's B half (N split)
        int eph = 1;
        for (int kt = 0; kt < KT; kt++) {
            const int s = kt & 3;
            MBARRIER_WAIT_PARITY(sb + SM_EMPTY_OFF + 8 * s, eph);
            if (s == 3) eph ^= 1;
            const int k0 = kt * BK;
            const uint32_t abase = sb + SM_A_OFF(s);
            #pragma unroll
            for (int i = 0; i < 8; i++) {
                int c = tid + i * 128;          // 0..1023
                int row = c >> 3, col = c & 7;  // 128 rows x 8 chunks
                uint32_t boff = (uint32_t)(row * 128 + col * 16);
                cp_async16(abase + SMEM_SWIZZLE_128B(boff),
                           Aq + (size_t)(bm_cta + row) * K_DIM + k0 + col * 8);
            }
            const uint32_t bbase = sb + SM_B_OFF(s);
            #pragma unroll
            for (int i = 0; i < 8; i++) {
                int c = tid + i * 128;          // 0..1023
                int row = c >> 3, col = c & 7;  // 128 rows x 8 chunks
                uint32_t boff = (uint32_t)(row * 128 + col * 16);
                cp_async16(bbase + SMEM_SWIZZLE_128B(boff),
                           Bq + (size_t)(bn_cta + row) * K_DIM + k0 + col * 8);
            }
            cp_commit();
            if (kt >= 2) {
                cp_wait<2>();
                FENCE_PROXY_ASYNC();
                MBARRIER_ARRIVE_RANK0(sb + SM_FULL_OFF + 8 * ((kt - 2) & 3));
            }
        }
        cp_wait<1>();
        FENCE_PROXY_ASYNC();
        MBARRIER_ARRIVE_RANK0(sb + SM_FULL_OFF + 8 * ((KT - 2) & 3));
        cp_wait<0>();
        FENCE_PROXY_ASYNC();
        MBARRIER_ARRIVE_RANK0(sb + SM_FULL_OFF + 8 * ((KT - 1) & 3));
    }
    // warps 5-7: nothing until completion wait

    // ---- everyone waits for MMA chain completion (multicast commit arrives per CTA) ----
    MBARRIER_WAIT_PARITY(sb + SM_DONE_OFF, 0);
    TCGEN05_FENCE_AFTER();

    if (wid < 4) {
        const float sc = g_sAB;
        const int row = bm_cta + wid * 32 + lane;
        float* __restrict__ crow = C + (size_t)row * N_DIM + bn;
        #pragma unroll
        for (int ch = 0; ch < 8; ch++) {
            uint32_t r[32];
            TCGEN05_LD_32X32B_X32(r, tmem + ch * 32);
            TCGEN05_WAIT_LD();
            #pragma unroll
            for (int j = 0; j < 8; j++) {
                float4 v;
                v.x = __uint_as_float(r[4 * j + 0]) * sc;
                v.y = __uint_as_float(r[4 * j + 1]) * sc;
                v.z = __uint_as_float(r[4 * j + 2]) * sc;
                v.w = __uint_as_float(r[4 * j + 3]) * sc;
                *(float4*)(crow + ch * 32 + 4 * j) = v;
            }
        }
        TCGEN05_FENCE_BEFORE();
    }
    __syncthreads();
    if (tid == 0) {
        #pragma unroll
        for (int s = 0; s < STAGES; s++) {
            MBARRIER_INVAL(sb + SM_FULL_OFF + 8 * s);
            MBARRIER_INVAL(sb + SM_EMPTY_OFF + 8 * s);
        }
        MBARRIER_INVAL(sb + SM_DONE_OFF);
    }
    __syncthreads();
    if (wid == 4) {
        TCGEN05_RELINQUISH_CG2();
        TCGEN05_DEALLOC_CG2(tmem, 256);
    }
    CLUSTER_SYNC();

#else
    // ================= fallback path (plain sm_103): mma.sync m16n8k16 =================
    // Grid is (32,16) with cluster (2,1,1): each CTA does 128 M-rows x 256 N-cols.
    const int bm = blockIdx.y * TILE_M + (int)(blockIdx.x & 1) * 128;
    const int bn = (int)(blockIdx.x >> 1) * BN;
    #define LDA_S 40
    __nv_bfloat16* As = (__nv_bfloat16*)smem;                 // 2*128*40*2 = 20480 B
    __nv_bfloat16* Bs = As + 2 * 128 * LDA_S;                 // 2*128*40*2 = 20480 B

    const int warpM = wid & 3;   // 4 warps along M (32 rows each)
    const int warpN = wid >> 2;  // 2 warps along N (64 cols each)
    const __nv_bfloat16* __restrict__ Aq = g_qA;
    const __nv_bfloat16* __restrict__ Bq = g_qB;

    for (int half = 0; half < 2; half++) {
        const int bnh = bn + half * 128;

        float acc[2][8][4];
        #pragma unroll
        for (int mt = 0; mt < 2; mt++)
            #pragma unroll
            for (int nt = 0; nt < 8; nt++)
                #pragma unroll
                for (int r = 0; r < 4; r++)
                    acc[mt][nt][r] = 0.0f;

        auto load_stage = [&](int kt, int buf) {
            const int k0 = kt * 32;
            #pragma unroll
            for (int c = tid; c < 512; c += 256) {
                int row = c >> 2, cc = c & 3;
                cp_async16(smem_u32(&As[(buf * 128 + row) * LDA_S + cc * 8]),
                           Aq + (size_t)(bm + row) * K_DIM + k0 + cc * 8);
            }
            #pragma unroll
            for (int c = tid; c < 512; c += 256) {
                int row = c >> 2, cc = c & 3;
                cp_async16(smem_u32(&Bs[(buf * 128 + row) * LDA_S + cc * 8]),
                           Bq + (size_t)(bnh + row) * K_DIM + k0 + cc * 8);
            }
            cp_commit();
        };

        const int KT32 = K_DIM / 32;  // 64
        __syncthreads();
        load_stage(0, 0);

        for (int kt = 0; kt < KT32; kt++) {
            const int buf = kt & 1;
            if (kt + 1 < KT32) {
                load_stage(kt + 1, (kt + 1) & 1);
                cp_wait<1>();
            } else {
                cp_wait<0>();
            }
            __syncthreads();

            #pragma unroll
            for (int ks = 0; ks < 2; ks++) {
                uint32_t a[2][4];
                #pragma unroll
                for (int mt = 0; mt < 2; mt++) {
                    const __nv_bfloat16* p =
                        &As[(buf * 128 + warpM * 32 + mt * 16 + (lane & 15)) * LDA_S + ks * 16 + (lane >> 4) * 8];
                    ldsm_x4(a[mt], smem_u32(p));
                }
                uint32_t b[8][2];
                #pragma unroll
                for (int np = 0; np < 4; np++) {
                    const __nv_bfloat16* p =
                        &Bs[(buf * 128 + warpN * 64 + np * 16 + (lane & 15)) * LDA_S + ks * 16 + (lane >> 4) * 8];
                    uint32_t r[4];
                    ldsm_x4(r, smem_u32(p));
                    b[2 * np][0] = r[0];     b[2 * np][1] = r[2];
                    b[2 * np + 1][0] = r[1]; b[2 * np + 1][1] = r[3];
                }
                #pragma unroll
                for (int mt = 0; mt < 2; mt++)
                    #pragma unroll
                    for (int nt = 0; nt < 8; nt++)
                        mma_bf16(acc[mt][nt], a[mt], b[nt]);
            }
            __syncthreads();
        }

        const float s = g_sAB;
        const int groupID = lane >> 2, tig = lane & 3;
        #pragma unroll
        for (int mt = 0; mt < 2; mt++) {
            #pragma unroll
            for (int nt = 0; nt < 8; nt++) {
                int row0 = bm + warpM * 32 + mt * 16 + groupID;
                int col  = bnh + warpN * 64 + nt * 8 + tig * 2;
                float2 v0 = make_float2(acc[mt][nt][0] * s, acc[mt][nt][1] * s);
                float2 v1 = make_float2(acc[mt][nt][2] * s, acc[mt][nt][3] * s);
                *(float2*)&C[(size_t)row0 * N_DIM + col]       = v0;
                *(float2*)&C[(size_t)(row0 + 8) * N_DIM + col] = v1;
            }
        }
    }
    #undef LDA_S
#endif
}

// ---------------- launch ----------------
extern "C" void kernel_launch(void* const* d_in, const int* in_sizes, int n_in,
                              void* d_out, int out_size) {
    const float* A = (const float*)d_in[0];  // [4096, 2048]
    const float* B = (const float*)d_in[1];  // [2048, 4096]
    float* C = (float*)d_out;                // [4096, 4096]

    const int nA = M_DIM * K_DIM;

    minmax_fused<<<2 * MMG, 256>>>(A, B);
    finalize_scales<<<1, 256>>>();

    quantize_A<<<(nA / 4 + 255) / 256, 256>>>(A, nA / 4);
    dim3 tgrid(N_DIM / 32, K_DIM / 32);
    quantize_B_T<<<tgrid, dim3(32, 8)>>>(B);

    cudaFuncSetAttribute(gemm_tc, cudaFuncAttributeMaxDynamicSharedMemorySize, SMEM_TOTAL);
    dim3 grid(2 * (N_DIM / BN), M_DIM / TILE_M);  // 32 x 16, clusters of 2 along x
    gemm_tc<<<grid, 256, SMEM_TOTAL>>>(C);
}

// round 13
// speedup vs baseline: 2.1858x; 2.1858x over previous
#include <cuda_runtime.h>
#include <cuda_bf16.h>
#include <cstdint>

// Problem shapes (fixed by setup_inputs)
#define M_DIM 4096
#define K_DIM 2048
#define N_DIM 4096

// Detect tcgen05 availability per compilation pass (compute_103a yes, compute_103 no)
#define HAS_TCGEN05 0
#ifdef __CUDA_ARCH__
#ifdef __CUDA_ARCH_HAS_FEATURE__
#if __CUDA_ARCH_HAS_FEATURE__(SM103_ALL) || __CUDA_ARCH_HAS_FEATURE__(SM100_ALL)
#undef HAS_TCGEN05
#define HAS_TCGEN05 1
#endif
#endif
#endif

// ---------------- device scratch (no allocation allowed) ----------------
__device__ __nv_bfloat16 g_qA[(size_t)M_DIM * K_DIM];   // centered quantized A (bf16), [M,K] K-major
__device__ __nv_bfloat16 g_qB[(size_t)N_DIM * K_DIM];   // centered quantized B^T (bf16), [N,K] K-major

#define MMG 1024
__device__ float g_pminA[MMG], g_pmaxA[MMG], g_pminB[MMG], g_pmaxB[MMG];
__device__ float g_scaleA, g_zeroA, g_scaleB, g_zeroB, g_sAB;

// ---------------- generic helpers (valid on all targets) ----------------
__device__ __forceinline__ uint32_t smem_u32(const void* p) {
    return (uint32_t)__cvta_generic_to_shared(p);
}
__device__ __forceinline__ void cp_async16(uint32_t dst, const void* src) {
    asm volatile("cp.async.cg.shared.global [%0], [%1], 16;\n" :: "r"(dst), "l"(src) : "memory");
}
__device__ __forceinline__ void cp_commit() {
    asm volatile("cp.async.commit_group;\n" ::: "memory");
}
template <int N>
__device__ __forceinline__ void cp_wait() {
    asm volatile("cp.async.wait_group %0;\n" :: "n"(N) : "memory");
}
__device__ __forceinline__ void ldsm_x4(uint32_t* r, uint32_t addr) {
    asm volatile("ldmatrix.sync.aligned.m8n8.x4.shared.b16 {%0,%1,%2,%3}, [%4];\n"
                 : "=r"(r[0]), "=r"(r[1]), "=r"(r[2]), "=r"(r[3]) : "r"(addr));
}
__device__ __forceinline__ void mma_bf16(float* d, const uint32_t* a, const uint32_t* b) {
    asm volatile("mma.sync.aligned.m16n8k16.row.col.f32.bf16.bf16.f32 "
                 "{%0,%1,%2,%3}, {%4,%5,%6,%7}, {%8,%9}, {%0,%1,%2,%3};\n"
                 : "+f"(d[0]), "+f"(d[1]), "+f"(d[2]), "+f"(d[3])
                 : "r"(a[0]), "r"(a[1]), "r"(a[2]), "r"(a[3]),
                   "r"(b[0]), "r"(b[1]));
}

#define SMEM_SWIZZLE_128B(byte_offset) ((byte_offset) ^ (((byte_offset) >> 3) & 0x70))

// ---------------- tcgen05-only helpers ----------------
#if HAS_TCGEN05
__device__ __forceinline__ uint32_t elect_one_pred() {
    uint32_t pred;
    asm volatile("{\n\t.reg .pred p;\n\telect.sync _|p, 0xFFFFFFFF;\n\tselp.b32 %0, 1, 0, p;\n\t}"
                 : "=r"(pred));
    return pred;
}

// SW128 K-major SMEM descriptor (Blackwell): layout=SW128, version=1, SBO=64, LBO=1
static constexpr uint64_t SMEM_DESC_BASE_SW128 =
    (uint64_t(2) << 61) | (uint64_t(1) << 46) | (uint64_t(64) << 32) | (uint64_t(1) << 16);
#define MAKE_SMEM_DESC(base_addr) \
    (SMEM_DESC_BASE_SW128 | ((uint64_t)((base_addr) >> 4) & 0x3FFF))

#define MBARRIER_INIT(mbar, count) \
    asm volatile("mbarrier.init.shared.b64 [%0], %1;" :: "r"((uint32_t)(mbar)), "r"((uint32_t)(count)) : "memory")
#define MBARRIER_INVAL(mbar) \
    asm volatile("mbarrier.inval.shared.b64 [%0];" :: "r"((uint32_t)(mbar)) : "memory")
#define MBARRIER_ARRIVE(mbar) \
    asm volatile("mbarrier.arrive.shared.b64 _, [%0];" :: "r"((uint32_t)(mbar)) : "memory")
#define MBARRIER_WAIT_PARITY(mbar, parity) do { \
    uint32_t _mbar = (uint32_t)(mbar); \
    uint32_t _par = (uint32_t)(parity); \
    uint32_t _done; \
    asm volatile("{\n\t.reg .pred p;\n\t" \
        "mbarrier.try_wait.parity.acquire.cta.shared::cta.b64 p, [%1], %2;\n\t" \
        "selp.b32 %0, 1, 0, p;\n\t}" : "=r"(_done) : "r"(_mbar), "r"(_par) : "memory"); \
    if (!_done) { \
        asm volatile("{\n\t.reg .pred P1;\n\t" \
            "WAIT_LOOP_%=:\n\t" \
            "mbarrier.try_wait.parity.acquire.cta.shared::cta.b64 P1, [%0], %1, 0x989680;\n\t" \
            "@P1 bra.uni WAIT_DONE_%=;\n\t" \
            "bra.uni WAIT_LOOP_%=;\n\t" \
            "WAIT_DONE_%=:\n\t}" :: "r"(_mbar), "r"(_par) : "memory"); \
    } \
} while (0)

#define FENCE_PROXY_ASYNC() \
    asm volatile("fence.proxy.async.shared::cta;" ::: "memory")
#define TCGEN05_FENCE_AFTER() \
    asm volatile("tcgen05.fence::after_thread_sync;" ::: "memory")
#define TCGEN05_FENCE_BEFORE() \
    asm volatile("tcgen05.fence::before_thread_sync;" ::: "memory")
#define TCGEN05_ALLOC(smem_addr, nCols) \
    asm volatile("tcgen05.alloc.cta_group::1.sync.aligned.shared::cta.b32 [%0], %1;" \
                 :: "r"((uint32_t)(smem_addr)), "r"((uint32_t)(nCols)) : "memory")
#define TCGEN05_DEALLOC(tmem, nCols) \
    asm volatile("tcgen05.dealloc.cta_group::1.sync.aligned.b32 %0, %1;" :: "r"(tmem), "r"((uint32_t)(nCols)))
#define TCGEN05_RELINQUISH() \
    asm volatile("tcgen05.relinquish_alloc_permit.cta_group::1.sync.aligned;")
#define TCGEN05_COMMIT(mbar) \
    asm volatile("tcgen05.commit.cta_group::1.mbarrier::arrive::one.shared::cluster.b64 [%0];" \
                 :: "r"((uint32_t)(mbar)) : "memory")
#define TCGEN05_WAIT_LD() \
    asm volatile("tcgen05.wait::ld.sync.aligned;" ::: "memory")

#define TCGEN05_LD_32X32B_X32(r, tmem_addr) \
    asm volatile("tcgen05.ld.sync.aligned.32x32b.x32.b32 " \
        "{%0, %1, %2, %3, %4, %5, %6, %7, %8, %9, %10, %11, %12, %13, %14, %15, " \
        "%16, %17, %18, %19, %20, %21, %22, %23, %24, %25, %26, %27, %28, %29, %30, %31}, [%32];" \
        : "=r"((r)[0]), "=r"((r)[1]), "=r"((r)[2]), "=r"((r)[3]), \
          "=r"((r)[4]), "=r"((r)[5]), "=r"((r)[6]), "=r"((r)[7]), \
          "=r"((r)[8]), "=r"((r)[9]), "=r"((r)[10]), "=r"((r)[11]), \
          "=r"((r)[12]), "=r"((r)[13]), "=r"((r)[14]), "=r"((r)[15]), \
          "=r"((r)[16]), "=r"((r)[17]), "=r"((r)[18]), "=r"((r)[19]), \
          "=r"((r)[20]), "=r"((r)[21]), "=r"((r)[22]), "=r"((r)[23]), \
          "=r"((r)[24]), "=r"((r)[25]), "=r"((r)[26]), "=r"((r)[27]), \
          "=r"((r)[28]), "=r"((r)[29]), "=r"((r)[30]), "=r"((r)[31]) \
        : "r"(tmem_addr))

__device__ __forceinline__ void mma_f16_ss(uint32_t d_tmem, uint64_t a_desc, uint64_t b_desc,
                                           uint32_t idesc, uint32_t enable_d) {
    asm volatile(
        "{\n\t.reg .pred p;\n\t"
        "setp.ne.u32 p, %4, 0;\n\t"
        "tcgen05.mma.cta_group::1.kind::f16 [%0], %1, %2, %3, {%5, %5, %5, %5}, p;\n\t}"
        :: "r"(d_tmem), "l"(a_desc), "l"(b_desc), "r"(idesc), "r"(enable_d), "r"(0u)
        : "memory");
}
#endif  // HAS_TCGEN05

// ---------------- 1) fused per-tensor min/max partials (A and B in one launch) ----------------
__global__ void minmax_fused(const float* __restrict__ A, const float* __restrict__ B) {
    const int which = (blockIdx.x >= MMG) ? 1 : 0;
    const int blk = which ? (blockIdx.x - MMG) : blockIdx.x;
    const float* __restrict__ x = which ? B : A;
    const int n4 = (which ? (K_DIM * N_DIM) : (M_DIM * K_DIM)) >> 2;

    float vmin = 3.4028235e38f, vmax = -3.4028235e38f;
    int idx = blk * blockDim.x + threadIdx.x;
    int stride = MMG * blockDim.x;
    const float4* x4 = (const float4*)x;
    for (int i = idx; i < n4; i += stride) {
        float4 v = x4[i];
        vmin = fminf(vmin, fminf(fminf(v.x, v.y), fminf(v.z, v.w)));
        vmax = fmaxf(vmax, fmaxf(fmaxf(v.x, v.y), fmaxf(v.z, v.w)));
    }
    #pragma unroll
    for (int o = 16; o > 0; o >>= 1) {
        vmin = fminf(vmin, __shfl_xor_sync(0xffffffffu, vmin, o));
        vmax = fmaxf(vmax, __shfl_xor_sync(0xffffffffu, vmax, o));
    }
    __shared__ float smin[8], smax[8];
    int warp = threadIdx.x >> 5, lane = threadIdx.x & 31;
    if (lane == 0) { smin[warp] = vmin; smax[warp] = vmax; }
    __syncthreads();
    if (threadIdx.x == 0) {
        float m0 = smin[0], m1 = smax[0];
        #pragma unroll
        for (int w = 1; w < 8; w++) { m0 = fminf(m0, smin[w]); m1 = fmaxf(m1, smax[w]); }
        if (which) { g_pminB[blk] = m0; g_pmaxB[blk] = m1; }
        else       { g_pminA[blk] = m0; g_pmaxA[blk] = m1; }
    }
}

// ---------------- 2) finalize scales/zeros ----------------
__global__ void finalize_scales() {
    __shared__ float s0[256], s1[256], s2[256], s3[256];
    int t = threadIdx.x;
    float mnA = 3.4028235e38f, mxA = -3.4028235e38f;
    float mnB = 3.4028235e38f, mxB = -3.4028235e38f;
    for (int i = t; i < MMG; i += 256) {
        mnA = fminf(mnA, g_pminA[i]); mxA = fmaxf(mxA, g_pmaxA[i]);
        mnB = fminf(mnB, g_pminB[i]); mxB = fmaxf(mxB, g_pmaxB[i]);
    }
    s0[t] = mnA; s1[t] = mxA; s2[t] = mnB; s3[t] = mxB;
    __syncthreads();
    for (int o = 128; o > 0; o >>= 1) {
        if (t < o) {
            s0[t] = fminf(s0[t], s0[t + o]);
            s1[t] = fmaxf(s1[t], s1[t + o]);
            s2[t] = fminf(s2[t], s2[t + o]);
            s3[t] = fmaxf(s3[t], s3[t + o]);
        }
        __syncthreads();
    }
    if (t == 0) {
        float sA = __fdiv_rn(s1[0] - s0[0], 255.0f);
        float zA = rintf(__fdiv_rn(-s0[0], sA));
        float sB = __fdiv_rn(s3[0] - s2[0], 255.0f);
        float zB = rintf(__fdiv_rn(-s2[0], sB));
        g_scaleA = sA; g_zeroA = zA;
        g_scaleB = sB; g_zeroB = zB;
        g_sAB = sA * sB;
    }
}

__device__ __forceinline__ float quant_center(float v, float s, float z) {
    return fminf(fmaxf(rintf(__fdiv_rn(v, s)) + z, 0.0f), 255.0f) - z;
}
__device__ __forceinline__ uint32_t pack_bf16x2(float a, float b) {
    __nv_bfloat162 p = make_bfloat162(__float2bfloat16_rn(a), __float2bfloat16_rn(b));
    uint32_t u;
    memcpy(&u, &p, 4);
    return u;
}

// ---------------- 3a) quantize A (centered, bf16) — 8 elems/thread, uint4 stores ----------------
__global__ void quantize_A(const float* __restrict__ x, int n8) {
    int i = blockIdx.x * blockDim.x + threadIdx.x;
    if (i >= n8) return;
    float s = g_scaleA, z = g_zeroA;
    float4 v0 = ((const float4*)x)[2 * i];
    float4 v1 = ((const float4*)x)[2 * i + 1];
    uint4 out;
    out.x = pack_bf16x2(quant_center(v0.x, s, z), quant_center(v0.y, s, z));
    out.y = pack_bf16x2(quant_center(v0.z, s, z), quant_center(v0.w, s, z));
    out.z = pack_bf16x2(quant_center(v1.x, s, z), quant_center(v1.y, s, z));
    out.w = pack_bf16x2(quant_center(v1.z, s, z), quant_center(v1.w, s, z));
    ((uint4*)g_qA)[i] = out;
}

// ---------------- 3b) quantize B + transpose: g_qB[n*K + k], vectorized ----------------
// 64(k) x 64(n) tile per block, 256 threads. float4 loads, uint4 (8x bf16) stores.
__global__ void quantize_B_T(const float* __restrict__ B) {
    __shared__ float tile[64][65];   // [n][k]
    const int n0 = blockIdx.x * 64, k0 = blockIdx.y * 64;
    const int t = threadIdx.x;
    #pragma unroll
    for (int i = 0; i < 4; i++) {
        int idx = t + i * 256;            // 0..1023
        int kk = idx >> 4, c4 = idx & 15; // 64 k-rows x 16 float4
        float4 v = *(const float4*)(B + (size_t)(k0 + kk) * N_DIM + n0 + c4 * 4);
        tile[c4 * 4 + 0][kk] = v.x;
        tile[c4 * 4 + 1][kk] = v.y;
        tile[c4 * 4 + 2][kk] = v.z;
        tile[c4 * 4 + 3][kk] = v.w;
    }
    __syncthreads();
    const float s = g_scaleB, z = g_zeroB;
    #pragma unroll
    for (int i = 0; i < 2; i++) {
        int o = t + i * 256;              // 0..511
        int nn = o >> 3, c8 = o & 7;      // 64 n-rows x 8 k-chunks
        float q[8];
        #pragma unroll
        for (int j = 0; j < 8; j++)
            q[j] = quant_center(tile[nn][c8 * 8 + j], s, z);
        uint4 out;
        out.x = pack_bf16x2(q[0], q[1]);
        out.y = pack_bf16x2(q[2], q[3]);
        out.z = pack_bf16x2(q[4], q[5]);
        out.w = pack_bf16x2(q[6], q[7]);
        *(uint4*)(g_qB + (size_t)(n0 + nn) * K_DIM + k0 + c8 * 8) = out;
    }
}

// ---------------- 4) GEMM: cg1 tcgen05, BM=256 (2 x M=128 dispatches), BN=256 ----------------
#define STAGES 3
#define BM 256
#define BN 256
#define BK 64
#define KT (K_DIM / BK)   // 32
// idesc per dispatch: dtype=F32(bit4), atype=BF16(bit7), btype=BF16(bit10), N/8<<17, M=128 -> 8<<24
#define GEMM_IDESC ((1u << 4) | (1u << 7) | (1u << 10) | ((BN / 8) << 17) | (8u << 24))

// dynamic SMEM layout — per stage: A0 16K | A1 16K | B 32K = 64K
#define SM_TPTR_OFF   0
#define SM_FULL_OFF   16
#define SM_EMPTY_OFF  48
#define SM_DONE_OFF   80
#define SM_STAGE(s)   (1024 + (s) * 65536)
#define SM_A0_OFF(s)  (SM_STAGE(s))
#define SM_A1_OFF(s)  (SM_STAGE(s) + 16384)
#define SM_B_OFF(s)   (SM_STAGE(s) + 32768)
#define SMEM_TOTAL    (1024 + STAGES * 65536)   // 197632

#define GEMM_THREADS 288   // warps 0-7 producers+epilogue, warp 8 MMA

__global__ void __launch_bounds__(GEMM_THREADS, 1) __cluster_dims__(1, 1, 1)
gemm_tc(float* __restrict__ C) {
    extern __shared__ char smem[];
    const int tid = threadIdx.x, wid = tid >> 5, lane = tid & 31;
    const int bm = blockIdx.y * BM;
    const int bn = blockIdx.x * BN;

#if HAS_TCGEN05
    // ================= tcgen05 path (sm_103a) =================
    const uint32_t sb = smem_u32(smem);

    if (tid == 0) {
        #pragma unroll
        for (int s = 0; s < STAGES; s++) {
            MBARRIER_INIT(sb + SM_FULL_OFF + 8 * s, 256);   // 256 producer threads
            MBARRIER_INIT(sb + SM_EMPTY_OFF + 8 * s, 1);    // commit arrival
        }
        MBARRIER_INIT(sb + SM_DONE_OFF, 1);
    }
    if (wid == 8) {
        TCGEN05_ALLOC(sb + SM_TPTR_OFF, 512);
    } else {
        TCGEN05_RELINQUISH();
    }
    __syncthreads();

    uint32_t tmem;
    asm volatile("ld.shared.b32 %0, [%1];" : "=r"(tmem) : "r"(sb + SM_TPTR_OFF));

    if (wid == 8) {
        // ---- MMA warp ----
        TCGEN05_FENCE_AFTER();
        int s = 0, ph = 0;
        for (int kt = 0; kt < KT; kt++) {
            MBARRIER_WAIT_PARITY(sb + SM_FULL_OFF + 8 * s, ph);
            if (elect_one_pred()) {
                const uint64_t ad0 = MAKE_SMEM_DESC(sb + SM_A0_OFF(s));
                const uint64_t ad1 = MAKE_SMEM_DESC(sb + SM_A1_OFF(s));
                const uint64_t bd  = MAKE_SMEM_DESC(sb + SM_B_OFF(s));
                #pragma unroll
                for (int ks = 0; ks < 4; ks++) {
                    uint32_t en = (kt > 0 || ks > 0) ? 1u : 0u;
                    mma_f16_ss(tmem,       ad0 + ks * 2, bd + ks * 2, GEMM_IDESC, en);
                    mma_f16_ss(tmem + 256, ad1 + ks * 2, bd + ks * 2, GEMM_IDESC, en);
                }
                TCGEN05_COMMIT(sb + SM_EMPTY_OFF + 8 * s);
            }
            if (++s == STAGES) { s = 0; ph ^= 1; }
        }
        if (elect_one_pred()) TCGEN05_COMMIT(sb + SM_DONE_OFF);
    } else {
        // ---- producer warps 0-7 (256 threads) ----
        const __nv_bfloat16* __restrict__ Aq = g_qA;
        const __nv_bfloat16* __restrict__ Bq = g_qB;
        int s = 0, eph = 1, arr = 0;
        for (int kt = 0; kt < KT; kt++) {
            MBARRIER_WAIT_PARITY(sb + SM_EMPTY_OFF + 8 * s, eph);
            const int k0 = kt * BK;
            // A: 256 rows x 8 chunks (rows 0-127 -> A0, 128-255 -> A1)
            const uint32_t a0base = sb + SM_A0_OFF(s);
            const uint32_t a1base = sb + SM_A1_OFF(s);
            #pragma unroll
            for (int i = 0; i < 8; i++) {
                int c = tid + i * 256;           // 0..2047
                int row = c >> 3, col = c & 7;   // 256 rows x 8 chunks
                uint32_t base = (row < 128) ? a0base : a1base;
                uint32_t boff = (uint32_t)((row & 127) * 128 + col * 16);
                cp_async16(base + SMEM_SWIZZLE_128B(boff),
                           Aq + (size_t)(bm + row) * K_DIM + k0 + col * 8);
            }
            // B: 256 rows x 8 chunks
            const uint32_t bbase = sb + SM_B_OFF(s);
            #pragma unroll
            for (int i = 0; i < 8; i++) {
                int c = tid + i * 256;
                int row = c >> 3, col = c & 7;
                uint32_t boff = (uint32_t)(row * 128 + col * 16);
                cp_async16(bbase + SMEM_SWIZZLE_128B(boff),
                           Bq + (size_t)(bn + row) * K_DIM + k0 + col * 8);
            }
            cp_commit();
            if (kt >= 2) {
                cp_wait<2>();
                FENCE_PROXY_ASYNC();
                MBARRIER_ARRIVE(sb + SM_FULL_OFF + 8 * arr);
                if (++arr == STAGES) arr = 0;
            }
            if (++s == STAGES) { s = 0; eph ^= 1; }
        }
        cp_wait<1>();
        FENCE_PROXY_ASYNC();
        MBARRIER_ARRIVE(sb + SM_FULL_OFF + 8 * arr);
        if (++arr == STAGES) arr = 0;
        cp_wait<0>();
        FENCE_PROXY_ASYNC();
        MBARRIER_ARRIVE(sb + SM_FULL_OFF + 8 * arr);
    }

    // ---- everyone waits for MMA chain completion ----
    MBARRIER_WAIT_PARITY(sb + SM_DONE_OFF, 0);
    TCGEN05_FENCE_AFTER();

    if (wid < 8) {
        // warps 0-3: D tile 0 (rows bm..bm+127, TMEM cols 0-255)
        // warps 4-7: D tile 1 (rows bm+128..bm+255, TMEM cols 256-511)
        // warp -> TMEM lane subpartition = wid % 4
        const float sc = g_sAB;
        const int tileI = wid >> 2;
        const int row = bm + tileI * 128 + (wid & 3) * 32 + lane;
        const uint32_t tbase = tmem + tileI * 256;
        float* __restrict__ crow = C + (size_t)row * N_DIM + bn;
        #pragma unroll
        for (int ch = 0; ch < 8; ch++) {
            uint32_t r[32];
            TCGEN05_LD_32X32B_X32(r, tbase + ch * 32);
            TCGEN05_WAIT_LD();
            #pragma unroll
            for (int j = 0; j < 8; j++) {
                float4 v;
                v.x = __uint_as_float(r[4 * j + 0]) * sc;
                v.y = __uint_as_float(r[4 * j + 1]) * sc;
                v.z = __uint_as_float(r[4 * j + 2]) * sc;
                v.w = __uint_as_float(r[4 * j + 3]) * sc;
                *(float4*)(crow + ch * 32 + 4 * j) = v;
            }
        }
        TCGEN05_FENCE_BEFORE();
    }
    __syncthreads();
    if (tid == 0) {
        #pragma unroll
        for (int s = 0; s < STAGES; s++) {
            MBARRIER_INVAL(sb + SM_FULL_OFF + 8 * s);
            MBARRIER_INVAL(sb + SM_EMPTY_OFF + 8 * s);
        }
        MBARRIER_INVAL(sb + SM_DONE_OFF);
    }
    __syncthreads();
    if (wid == 8) {
        TCGEN05_DEALLOC(tmem, 512);
    }

#else
    // ================= fallback path (plain sm_103): mma.sync m16n8k16 =================
    // Each CTA: 256x256 tile as 2 (M) x 2 (N) passes of 128x128. Warps 8 idles in compute.
    #define LDA_S 40
    __nv_bfloat16* As = (__nv_bfloat16*)smem;                 // 2*128*40*2 = 20480 B
    __nv_bfloat16* Bs = As + 2 * 128 * LDA_S;                 // 2*128*40*2 = 20480 B

    const int warpM = wid & 3;
    const int warpN = (wid >> 2) & 1;
    const __nv_bfloat16* __restrict__ Aq = g_qA;
    const __nv_bfloat16* __restrict__ Bq = g_qB;

    for (int mh = 0; mh < 2; mh++) {
        const int bmh = bm + mh * 128;
        for (int half = 0; half < 2; half++) {
            const int bnh = bn + half * 128;

            float acc[2][8][4];
            #pragma unroll
            for (int mt = 0; mt < 2; mt++)
                #pragma unroll
                for (int nt = 0; nt < 8; nt++)
                    #pragma unroll
                    for (int r = 0; r < 4; r++)
                        acc[mt][nt][r] = 0.0f;

            auto load_stage = [&](int kt, int buf) {
                const int k0 = kt * 32;
                for (int c = tid; c < 512; c += GEMM_THREADS) {
                    int row = c >> 2, cc = c & 3;
                    cp_async16(smem_u32(&As[(buf * 128 + row) * LDA_S + cc * 8]),
                               Aq + (size_t)(bmh + row) * K_DIM + k0 + cc * 8);
                }
                for (int c = tid; c < 512; c += GEMM_THREADS) {
                    int row = c >> 2, cc = c & 3;
                    cp_async16(smem_u32(&Bs[(buf * 128 + row) * LDA_S + cc * 8]),
                               Bq + (size_t)(bnh + row) * K_DIM + k0 + cc * 8);
                }
                cp_commit();
            };

            const int KT32 = K_DIM / 32;  // 64
            __syncthreads();
            load_stage(0, 0);

            for (int kt = 0; kt < KT32; kt++) {
                const int buf = kt & 1;
                if (kt + 1 < KT32) {
                    load_stage(kt + 1, (kt + 1) & 1);
                    cp_wait<1>();
                } else {
                    cp_wait<0>();
                }
                __syncthreads();

                if (wid < 8) {
                    #pragma unroll
                    for (int ks = 0; ks < 2; ks++) {
                        uint32_t a[2][4];
                        #pragma unroll
                        for (int mt = 0; mt < 2; mt++) {
                            const __nv_bfloat16* p =
                                &As[(buf * 128 + warpM * 32 + mt * 16 + (lane & 15)) * LDA_S + ks * 16 + (lane >> 4) * 8];
                            ldsm_x4(a[mt], smem_u32(p));
                        }
                        uint32_t b[8][2];
                        #pragma unroll
                        for (int np = 0; np < 4; np++) {
                            const __nv_bfloat16* p =
                                &Bs[(buf * 128 + warpN * 64 + np * 16 + (lane & 15)) * LDA_S + ks * 16 + (lane >> 4) * 8];
                            uint32_t r[4];
                            ldsm_x4(r, smem_u32(p));
                            b[2 * np][0] = r[0];     b[2 * np][1] = r[2];
                            b[2 * np + 1][0] = r[1]; b[2 * np + 1][1] = r[3];
                        }
                        #pragma unroll
                        for (int mt = 0; mt < 2; mt++)
                            #pragma unroll
                            for (int nt = 0; nt < 8; nt++)
                                mma_bf16(acc[mt][nt], a[mt], b[nt]);
                    }
                }
                __syncthreads();
            }

            if (wid < 8) {
                const float s = g_sAB;
                const int groupID = lane >> 2, tig = lane & 3;
                #pragma unroll
                for (int mt = 0; mt < 2; mt++) {
                    #pragma unroll
                    for (int nt = 0; nt < 8; nt++) {
                        int row0 = bmh + warpM * 32 + mt * 16 + groupID;
                        int col  = bnh + warpN * 64 + nt * 8 + tig * 2;
                        float2 v0 = make_float2(acc[mt][nt][0] * s, acc[mt][nt][1] * s);
                        float2 v1 = make_float2(acc[mt][nt][2] * s, acc[mt][nt][3] * s);
                        *(float2*)&C[(size_t)row0 * N_DIM + col]       = v0;
                        *(float2*)&C[(size_t)(row0 + 8) * N_DIM + col] = v1;
                    }
                }
            }
        }
    }
    #undef LDA_S
#endif
}

// ---------------- launch ----------------
extern "C" void kernel_launch(void* const* d_in, const int* in_sizes, int n_in,
                              void* d_out, int out_size) {
    const float* A = (const float*)d_in[0];  // [4096, 2048]
    const float* B = (const float*)d_in[1];  // [2048, 4096]
    float* C = (float*)d_out;                // [4096, 4096]

    const int nA = M_DIM * K_DIM;

    minmax_fused<<<2 * MMG, 256>>>(A, B);
    finalize_scales<<<1, 256>>>();

    quantize_A<<<(nA / 8 + 255) / 256, 256>>>(A, nA / 8);
    dim3 tgrid(N_DIM / 64, K_DIM / 64);
    quantize_B_T<<<tgrid, 256>>>(B);

    cudaFuncSetAttribute(gemm_tc, cudaFuncAttributeMaxDynamicSharedMemorySize, SMEM_TOTAL);
    dim3 grid(N_DIM / BN, M_DIM / BM);  // 16 x 16
    gemm_tc<<<grid, GEMM_THREADS, SMEM_TOTAL>>>(C);
}

// round 17
// speedup vs baseline: 2.5377x; 1.1610x over previous
#include <cuda_runtime.h>
#include <cuda_bf16.h>
#include <cstdint>

// Problem shapes (fixed by setup_inputs)
#define M_DIM 4096
#define K_DIM 2048
#define N_DIM 4096

// Detect tcgen05 availability per compilation pass (compute_103a yes, compute_103 no)
#define HAS_TCGEN05 0
#ifdef __CUDA_ARCH__
#ifdef __CUDA_ARCH_HAS_FEATURE__
#if __CUDA_ARCH_HAS_FEATURE__(SM103_ALL) || __CUDA_ARCH_HAS_FEATURE__(SM100_ALL)
#undef HAS_TCGEN05
#define HAS_TCGEN05 1
#endif
#endif
#endif

// ---------------- device scratch (no allocation allowed) ----------------
__device__ __nv_bfloat16 g_qA[(size_t)M_DIM * K_DIM];   // centered quantized A (bf16), [M,K] K-major
__device__ __nv_bfloat16 g_qB[(size_t)N_DIM * K_DIM];   // centered quantized B^T (bf16), [N,K] K-major

#define MMG 1024
__device__ float g_pminA[MMG], g_pmaxA[MMG], g_pminB[MMG], g_pmaxB[MMG];
__device__ float g_scaleA, g_zeroA, g_scaleB, g_zeroB, g_sAB;

// ---------------- generic helpers (valid on all targets) ----------------
__device__ __forceinline__ uint32_t smem_u32(const void* p) {
    return (uint32_t)__cvta_generic_to_shared(p);
}
__device__ __forceinline__ void cp_async16(uint32_t dst, const void* src) {
    asm volatile("cp.async.cg.shared.global [%0], [%1], 16;\n" :: "r"(dst), "l"(src) : "memory");
}
__device__ __forceinline__ void cp_commit() {
    asm volatile("cp.async.commit_group;\n" ::: "memory");
}
template <int N>
__device__ __forceinline__ void cp_wait() {
    asm volatile("cp.async.wait_group %0;\n" :: "n"(N) : "memory");
}
__device__ __forceinline__ void ldsm_x4(uint32_t* r, uint32_t addr) {
    asm volatile("ldmatrix.sync.aligned.m8n8.x4.shared.b16 {%0,%1,%2,%3}, [%4];\n"
                 : "=r"(r[0]), "=r"(r[1]), "=r"(r[2]), "=r"(r[3]) : "r"(addr));
}
__device__ __forceinline__ void mma_bf16(float* d, const uint32_t* a, const uint32_t* b) {
    asm volatile("mma.sync.aligned.m16n8k16.row.col.f32.bf16.bf16.f32 "
                 "{%0,%1,%2,%3}, {%4,%5,%6,%7}, {%8,%9}, {%0,%1,%2,%3};\n"
                 : "+f"(d[0]), "+f"(d[1]), "+f"(d[2]), "+f"(d[3])
                 : "r"(a[0]), "r"(a[1]), "r"(a[2]), "r"(a[3]),
                   "r"(b[0]), "r"(b[1]));
}

#define SMEM_SWIZZLE_128B(byte_offset) ((byte_offset) ^ (((byte_offset) >> 3) & 0x70))

// ---------------- tcgen05-only helpers ----------------
#if HAS_TCGEN05
__device__ __forceinline__ uint32_t elect_one_pred() {
    uint32_t pred;
    asm volatile("{\n\t.reg .pred p;\n\telect.sync _|p, 0xFFFFFFFF;\n\tselp.b32 %0, 1, 0, p;\n\t}"
                 : "=r"(pred));
    return pred;
}

// SW128 K-major SMEM descriptor (Blackwell): layout=SW128, version=1, SBO=64, LBO=1
static constexpr uint64_t SMEM_DESC_BASE_SW128 =
    (uint64_t(2) << 61) | (uint64_t(1) << 46) | (uint64_t(64) << 32) | (uint64_t(1) << 16);
#define MAKE_SMEM_DESC(base_addr) \
    (SMEM_DESC_BASE_SW128 | ((uint64_t)((base_addr) >> 4) & 0x3FFF))

#define MBARRIER_INIT(mbar, count) \
    asm volatile("mbarrier.init.shared.b64 [%0], %1;" :: "r"((uint32_t)(mbar)), "r"((uint32_t)(count)) : "memory")
#define MBARRIER_INVAL(mbar) \
    asm volatile("mbarrier.inval.shared.b64 [%0];" :: "r"((uint32_t)(mbar)) : "memory")
#define MBARRIER_ARRIVE(mbar) \
    asm volatile("mbarrier.arrive.shared.b64 _, [%0];" :: "r"((uint32_t)(mbar)) : "memory")
#define MBARRIER_WAIT_PARITY(mbar, parity) do { \
    uint32_t _mbar = (uint32_t)(mbar); \
    uint32_t _par = (uint32_t)(parity); \
    uint32_t _done; \
    asm volatile("{\n\t.reg .pred p;\n\t" \
        "mbarrier.try_wait.parity.acquire.cta.shared::cta.b64 p, [%1], %2;\n\t" \
        "selp.b32 %0, 1, 0, p;\n\t}" : "=r"(_done) : "r"(_mbar), "r"(_par) : "memory"); \
    if (!_done) { \
        asm volatile("{\n\t.reg .pred P1;\n\t" \
            "WAIT_LOOP_%=:\n\t" \
            "mbarrier.try_wait.parity.acquire.cta.shared::cta.b64 P1, [%0], %1, 0x989680;\n\t" \
            "@P1 bra.uni WAIT_DONE_%=;\n\t" \
            "bra.uni WAIT_LOOP_%=;\n\t" \
            "WAIT_DONE_%=:\n\t}" :: "r"(_mbar), "r"(_par) : "memory"); \
    } \
} while (0)

#define FENCE_PROXY_ASYNC() \
    asm volatile("fence.proxy.async.shared::cta;" ::: "memory")
#define TCGEN05_FENCE_AFTER() \
    asm volatile("tcgen05.fence::after_thread_sync;" ::: "memory")
#define TCGEN05_FENCE_BEFORE() \
    asm volatile("tcgen05.fence::before_thread_sync;" ::: "memory")
#define TCGEN05_ALLOC(smem_addr, nCols) \
    asm volatile("tcgen05.alloc.cta_group::1.sync.aligned.shared::cta.b32 [%0], %1;" \
                 :: "r"((uint32_t)(smem_addr)), "r"((uint32_t)(nCols)) : "memory")
#define TCGEN05_DEALLOC(tmem, nCols) \
    asm volatile("tcgen05.dealloc.cta_group::1.sync.aligned.b32 %0, %1;" :: "r"(tmem), "r"((uint32_t)(nCols)))
#define TCGEN05_RELINQUISH() \
    asm volatile("tcgen05.relinquish_alloc_permit.cta_group::1.sync.aligned;")
#define TCGEN05_COMMIT(mbar) \
    asm volatile("tcgen05.commit.cta_group::1.mbarrier::arrive::one.shared::cluster.b64 [%0];" \
                 :: "r"((uint32_t)(mbar)) : "memory")
#define TCGEN05_WAIT_LD() \
    asm volatile("tcgen05.wait::ld.sync.aligned;" ::: "memory")

#define TCGEN05_LD_32X32B_X32(r, tmem_addr) \
    asm volatile("tcgen05.ld.sync.aligned.32x32b.x32.b32 " \
        "{%0, %1, %2, %3, %4, %5, %6, %7, %8, %9, %10, %11, %12, %13, %14, %15, " \
        "%16, %17, %18, %19, %20, %21, %22, %23, %24, %25, %26, %27, %28, %29, %30, %31}, [%32];" \
        : "=r"((r)[0]), "=r"((r)[1]), "=r"((r)[2]), "=r"((r)[3]), \
          "=r"((r)[4]), "=r"((r)[5]), "=r"((r)[6]), "=r"((r)[7]), \
          "=r"((r)[8]), "=r"((r)[9]), "=r"((r)[10]), "=r"((r)[11]), \
          "=r"((r)[12]), "=r"((r)[13]), "=r"((r)[14]), "=r"((r)[15]), \
          "=r"((r)[16]), "=r"((r)[17]), "=r"((r)[18]), "=r"((r)[19]), \
          "=r"((r)[20]), "=r"((r)[21]), "=r"((r)[22]), "=r"((r)[23]), \
          "=r"((r)[24]), "=r"((r)[25]), "=r"((r)[26]), "=r"((r)[27]), \
          "=r"((r)[28]), "=r"((r)[29]), "=r"((r)[30]), "=r"((r)[31]) \
        : "r"(tmem_addr))

__device__ __forceinline__ void mma_f16_ss(uint32_t d_tmem, uint64_t a_desc, uint64_t b_desc,
                                           uint32_t idesc, uint32_t enable_d) {
    asm volatile(
        "{\n\t.reg .pred p;\n\t"
        "setp.ne.u32 p, %4, 0;\n\t"
        "tcgen05.mma.cta_group::1.kind::f16 [%0], %1, %2, %3, {%5, %5, %5, %5}, p;\n\t}"
        :: "r"(d_tmem), "l"(a_desc), "l"(b_desc), "r"(idesc), "r"(enable_d), "r"(0u)
        : "memory");
}
#endif  // HAS_TCGEN05

// ---------------- 1) fused per-tensor min/max partials (A and B in one launch) ----------------
__global__ void minmax_fused(const float* __restrict__ A, const float* __restrict__ B) {
    const int which = (blockIdx.x >= MMG) ? 1 : 0;
    const int blk = which ? (blockIdx.x - MMG) : blockIdx.x;
    const float* __restrict__ x = which ? B : A;
    const int n4 = (which ? (K_DIM * N_DIM) : (M_DIM * K_DIM)) >> 2;

    float vmin = 3.4028235e38f, vmax = -3.4028235e38f;
    int idx = blk * blockDim.x + threadIdx.x;
    int stride = MMG * blockDim.x;
    const float4* x4 = (const float4*)x;
    for (int i = idx; i < n4; i += stride) {
        float4 v = x4[i];
        vmin = fminf(vmin, fminf(fminf(v.x, v.y), fminf(v.z, v.w)));
        vmax = fmaxf(vmax, fmaxf(fmaxf(v.x, v.y), fmaxf(v.z, v.w)));
    }
    #pragma unroll
    for (int o = 16; o > 0; o >>= 1) {
        vmin = fminf(vmin, __shfl_xor_sync(0xffffffffu, vmin, o));
        vmax = fmaxf(vmax, __shfl_xor_sync(0xffffffffu, vmax, o));
    }
    __shared__ float smin[8], smax[8];
    int warp = threadIdx.x >> 5, lane = threadIdx.x & 31;
    if (lane == 0) { smin[warp] = vmin; smax[warp] = vmax; }
    __syncthreads();
    if (threadIdx.x == 0) {
        float m0 = smin[0], m1 = smax[0];
        #pragma unroll
        for (int w = 1; w < 8; w++) { m0 = fminf(m0, smin[w]); m1 = fmaxf(m1, smax[w]); }
        if (which) { g_pminB[blk] = m0; g_pmaxB[blk] = m1; }
        else       { g_pminA[blk] = m0; g_pmaxA[blk] = m1; }
    }
}

// ---------------- 2) finalize scales/zeros ----------------
__global__ void finalize_scales() {
    __shared__ float s0[256], s1[256], s2[256], s3[256];
    int t = threadIdx.x;
    float mnA = 3.4028235e38f, mxA = -3.4028235e38f;
    float mnB = 3.4028235e38f, mxB = -3.4028235e38f;
    for (int i = t; i < MMG; i += 256) {
        mnA = fminf(mnA, g_pminA[i]); mxA = fmaxf(mxA, g_pmaxA[i]);
        mnB = fminf(mnB, g_pminB[i]); mxB = fmaxf(mxB, g_pmaxB[i]);
    }
    s0[t] = mnA; s1[t] = mxA; s2[t] = mnB; s3[t] = mxB;
    __syncthreads();
    for (int o = 128; o > 0; o >>= 1) {
        if (t < o) {
            s0[t] = fminf(s0[t], s0[t + o]);
            s1[t] = fmaxf(s1[t], s1[t + o]);
            s2[t] = fminf(s2[t], s2[t + o]);
            s3[t] = fmaxf(s3[t], s3[t + o]);
        }
        __syncthreads();
    }
    if (t == 0) {
        float sA = __fdiv_rn(s1[0] - s0[0], 255.0f);
        float zA = rintf(__fdiv_rn(-s0[0], sA));
        float sB = __fdiv_rn(s3[0] - s2[0], 255.0f);
        float zB = rintf(__fdiv_rn(-s2[0], sB));
        g_scaleA = sA; g_zeroA = zA;
        g_scaleB = sB; g_zeroB = zB;
        g_sAB = sA * sB;
    }
}

__device__ __forceinline__ float quant_center(float v, float s, float z) {
    return fminf(fmaxf(rintf(__fdiv_rn(v, s)) + z, 0.0f), 255.0f) - z;
}
__device__ __forceinline__ uint32_t pack_bf16x2(float a, float b) {
    __nv_bfloat162 p = make_bfloat162(__float2bfloat16_rn(a), __float2bfloat16_rn(b));
    uint32_t u;
    memcpy(&u, &p, 4);
    return u;
}

// ---------------- 3a) quantize A (centered, bf16) — 8 elems/thread, uint4 stores ----------------
__global__ void quantize_A(const float* __restrict__ x, int n8) {
    int i = blockIdx.x * blockDim.x + threadIdx.x;
    if (i >= n8) return;
    float s = g_scaleA, z = g_zeroA;
    float4 v0 = ((const float4*)x)[2 * i];
    float4 v1 = ((const float4*)x)[2 * i + 1];
    uint4 out;
    out.x = pack_bf16x2(quant_center(v0.x, s, z), quant_center(v0.y, s, z));
    out.y = pack_bf16x2(quant_center(v0.z, s, z), quant_center(v0.w, s, z));
    out.z = pack_bf16x2(quant_center(v1.x, s, z), quant_center(v1.y, s, z));
    out.w = pack_bf16x2(quant_center(v1.z, s, z), quant_center(v1.w, s, z));
    ((uint4*)g_qA)[i] = out;
}

// ---------------- 3b) quantize B + transpose: g_qB[n*K + k], vectorized ----------------
// 64(k) x 64(n) tile per block, 256 threads. float4 loads, uint4 (8x bf16) stores.
__global__ void quantize_B_T(const float* __restrict__ B) {
    __shared__ float tile[64][65];   // [n][k]
    const int n0 = blockIdx.x * 64, k0 = blockIdx.y * 64;
    const int t = threadIdx.x;
    #pragma unroll
    for (int i = 0; i < 4; i++) {
        int idx = t + i * 256;            // 0..1023
        int kk = idx >> 4, c4 = idx & 15; // 64 k-rows x 16 float4
        float4 v = *(const float4*)(B + (size_t)(k0 + kk) * N_DIM + n0 + c4 * 4);
        tile[c4 * 4 + 0][kk] = v.x;
        tile[c4 * 4 + 1][kk] = v.y;
        tile[c4 * 4 + 2][kk] = v.z;
        tile[c4 * 4 + 3][kk] = v.w;
    }
    __syncthreads();
    const float s = g_scaleB, z = g_zeroB;
    #pragma unroll
    for (int i = 0; i < 2; i++) {
        int o = t + i * 256;              // 0..511
        int nn = o >> 3, c8 = o & 7;      // 64 n-rows x 8 k-chunks
        float q[8];
        #pragma unroll
        for (int j = 0; j < 8; j++)
            q[j] = quant_center(tile[nn][c8 * 8 + j], s, z);
        uint4 out;
        out.x = pack_bf16x2(q[0], q[1]);
        out.y = pack_bf16x2(q[2], q[3]);
        out.z = pack_bf16x2(q[4], q[5]);
        out.w = pack_bf16x2(q[6], q[7]);
        *(uint4*)(g_qB + (size_t)(n0 + nn) * K_DIM + k0 + c8 * 8) = out;
    }
}

// ---------------- 4) GEMM: tcgen05 cg1 (exact R8 config) ----------------
#define STAGES 4
#define BM 128
#define BN 256
#define BK 64
#define KT (K_DIM / BK)   // 32
// idesc: dtype=F32(bit4), atype=BF16(bit7), btype=BF16(bit10), N/8<<17, M/16<<24
#define GEMM_IDESC ((1u << 4) | (1u << 7) | (1u << 10) | ((BN / 8) << 17) | ((BM / 16) << 24))

// dynamic SMEM layout (tcgen05 path)
#define SM_TPTR_OFF   0
#define SM_FULL_OFF   16
#define SM_EMPTY_OFF  48
#define SM_DONE_OFF   80
#define SM_A_OFF(s)   (1024 + (s) * 16384)        // 128 rows x 128B per stage
#define SM_B_OFF(s)   (66560 + (s) * 32768)       // 256 rows x 128B per stage
#define SMEM_TOTAL    197632

__global__ void __launch_bounds__(256, 1) __cluster_dims__(1, 1, 1)
gemm_tc(float* __restrict__ C) {
    extern __shared__ char smem[];
    const int tid = threadIdx.x, wid = tid >> 5, lane = tid & 31;
    const int bm = blockIdx.y * BM;
    const int bn = blockIdx.x * BN;

#if HAS_TCGEN05
    // ================= tcgen05 path (sm_103a) =================
    const uint32_t sb = smem_u32(smem);

    if (tid == 0) {
        #pragma unroll
        for (int s = 0; s < STAGES; s++) {
            MBARRIER_INIT(sb + SM_FULL_OFF + 8 * s, 128);
            MBARRIER_INIT(sb + SM_EMPTY_OFF + 8 * s, 1);
        }
        MBARRIER_INIT(sb + SM_DONE_OFF, 1);
    }
    if (wid == 4) {
        TCGEN05_ALLOC(sb + SM_TPTR_OFF, 256);
    } else {
        TCGEN05_RELINQUISH();
    }
    __syncthreads();

    uint32_t tmem;
    asm volatile("ld.shared.b32 %0, [%1];" : "=r"(tmem) : "r"(sb + SM_TPTR_OFF));

    if (wid == 4) {
        // ---- MMA warp ----
        TCGEN05_FENCE_AFTER();
        int ph = 0;
        for (int kt = 0; kt < KT; kt++) {
            const int s = kt & 3;
            MBARRIER_WAIT_PARITY(sb + SM_FULL_OFF + 8 * s, ph);
            if (s == 3) ph ^= 1;
            if (elect_one_pred()) {
                const uint64_t ad = MAKE_SMEM_DESC(sb + SM_A_OFF(s));
                const uint64_t bd = MAKE_SMEM_DESC(sb + SM_B_OFF(s));
                #pragma unroll
                for (int ks = 0; ks < 4; ks++) {
                    uint32_t en = (kt > 0 || ks > 0) ? 1u : 0u;
                    mma_f16_ss(tmem, ad + ks * 2, bd + ks * 2, GEMM_IDESC, en);
                }
                TCGEN05_COMMIT(sb + SM_EMPTY_OFF + 8 * s);
            }
        }
        if (elect_one_pred()) TCGEN05_COMMIT(sb + SM_DONE_OFF);
    } else if (wid < 4) {
        // ---- producer warps 0-3 (128 threads) ----
        const __nv_bfloat16* __restrict__ Aq = g_qA;
        const __nv_bfloat16* __restrict__ Bq = g_qB;
        int eph = 1;
        for (int kt = 0; kt < KT; kt++) {
            const int s = kt & 3;
            MBARRIER_WAIT_PARITY(sb + SM_EMPTY_OFF + 8 * s, eph);
            if (s == 3) eph ^= 1;
            const int k0 = kt * BK;
            const uint32_t abase = sb + SM_A_OFF(s);
            #pragma unroll
            for (int i = 0; i < 8; i++) {
                int c = tid + i * 128;          // 0..1023
                int row = c >> 3, col = c & 7;  // 128 rows x 8 chunks
                uint32_t boff = (uint32_t)(row * 128 + col * 16);
                cp_async16(abase + SMEM_SWIZZLE_128B(boff),
                           Aq + (size_t)(bm + row) * K_DIM + k0 + col * 8);
            }
            const uint32_t bbase = sb + SM_B_OFF(s);
            #pragma unroll
            for (int i = 0; i < 16; i++) {
                int c = tid + i * 128;          // 0..2047
                int row = c >> 3, col = c & 7;  // 256 rows x 8 chunks
                uint32_t boff = (uint32_t)(row * 128 + col * 16);
                cp_async16(bbase + SMEM_SWIZZLE_128B(boff),
                           Bq + (size_t)(bn + row) * K_DIM + k0 + col * 8);
            }
            cp_commit();
            if (kt >= 2) {
                cp_wait<2>();
                FENCE_PROXY_ASYNC();
                MBARRIER_ARRIVE(sb + SM_FULL_OFF + 8 * ((kt - 2) & 3));
            }
        }
        cp_wait<1>();
        FENCE_PROXY_ASYNC();
        MBARRIER_ARRIVE(sb + SM_FULL_OFF + 8 * ((KT - 2) & 3));
        cp_wait<0>();
        FENCE_PROXY_ASYNC();
        MBARRIER_ARRIVE(sb + SM_FULL_OFF + 8 * ((KT - 1) & 3));
    }
    // warps 5-7: nothing until completion wait

    // ---- everyone waits for MMA chain completion ----
    MBARRIER_WAIT_PARITY(sb + SM_DONE_OFF, 0);
    TCGEN05_FENCE_AFTER();

    if (wid < 4) {
        const float sc = g_sAB;
        const int row = bm + wid * 32 + lane;
        float* __restrict__ crow = C + (size_t)row * N_DIM + bn;
        #pragma unroll
        for (int ch = 0; ch < 8; ch++) {
            uint32_t r[32];
            TCGEN05_LD_32X32B_X32(r, tmem + ch * 32);
            TCGEN05_WAIT_LD();
            #pragma unroll
            for (int j = 0; j < 8; j++) {
                float4 v;
                v.x = __uint_as_float(r[4 * j + 0]) * sc;
                v.y = __uint_as_float(r[4 * j + 1]) * sc;
                v.z = __uint_as_float(r[4 * j + 2]) * sc;
                v.w = __uint_as_float(r[4 * j + 3]) * sc;
                *(float4*)(crow + ch * 32 + 4 * j) = v;
            }
        }
        TCGEN05_FENCE_BEFORE();
    }
    __syncthreads();
    if (tid == 0) {
        #pragma unroll
        for (int s = 0; s < STAGES; s++) {
            MBARRIER_INVAL(sb + SM_FULL_OFF + 8 * s);
            MBARRIER_INVAL(sb + SM_EMPTY_OFF + 8 * s);
        }
        MBARRIER_INVAL(sb + SM_DONE_OFF);
    }
    __syncthreads();
    if (wid == 4) {
        TCGEN05_DEALLOC(tmem, 256);
    }

#else
    // ================= fallback path (plain sm_103): mma.sync m16n8k16 =================
    // Processes the 128x256 block tile as two 128x128 halves.
    #define LDA_S 40
    __nv_bfloat16* As = (__nv_bfloat16*)smem;                 // 2*128*40*2 = 20480 B
    __nv_bfloat16* Bs = As + 2 * 128 * LDA_S;                 // 2*128*40*2 = 20480 B

    const int warpM = wid & 3;   // 4 warps along M (32 rows each)
    const int warpN = wid >> 2;  // 2 warps along N (64 cols each)
    const __nv_bfloat16* __restrict__ Aq = g_qA;
    const __nv_bfloat16* __restrict__ Bq = g_qB;

    for (int half = 0; half < 2; half++) {
        const int bnh = bn + half * 128;

        float acc[2][8][4];
        #pragma unroll
        for (int mt = 0; mt < 2; mt++)
            #pragma unroll
            for (int nt = 0; nt < 8; nt++)
                #pragma unroll
                for (int r = 0; r < 4; r++)
                    acc[mt][nt][r] = 0.0f;

        auto load_stage = [&](int kt, int buf) {
            const int k0 = kt * 32;
            #pragma unroll
            for (int c = tid; c < 512; c += 256) {
                int row = c >> 2, cc = c & 3;
                cp_async16(smem_u32(&As[(buf * 128 + row) * LDA_S + cc * 8]),
                           Aq + (size_t)(bm + row) * K_DIM + k0 + cc * 8);
            }
            #pragma unroll
            for (int c = tid; c < 512; c += 256) {
                int row = c >> 2, cc = c & 3;
                cp_async16(smem_u32(&Bs[(buf * 128 + row) * LDA_S + cc * 8]),
                           Bq + (size_t)(bnh + row) * K_DIM + k0 + cc * 8);
            }
            cp_commit();
        };

        const int KT32 = K_DIM / 32;  // 64
        __syncthreads();
        load_stage(0, 0);

        for (int kt = 0; kt < KT32; kt++) {
            const int buf = kt & 1;
            if (kt + 1 < KT32) {
                load_stage(kt + 1, (kt + 1) & 1);
                cp_wait<1>();
            } else {
                cp_wait<0>();
            }
            __syncthreads();

            #pragma unroll
            for (int ks = 0; ks < 2; ks++) {
                uint32_t a[2][4];
                #pragma unroll
                for (int mt = 0; mt < 2; mt++) {
                    const __nv_bfloat16* p =
                        &As[(buf * 128 + warpM * 32 + mt * 16 + (lane & 15)) * LDA_S + ks * 16 + (lane >> 4) * 8];
                    ldsm_x4(a[mt], smem_u32(p));
                }
                uint32_t b[8][2];
                #pragma unroll
                for (int np = 0; np < 4; np++) {
                    const __nv_bfloat16* p =
                        &Bs[(buf * 128 + warpN * 64 + np * 16 + (lane & 15)) * LDA_S + ks * 16 + (lane >> 4) * 8];
                    uint32_t r[4];
                    ldsm_x4(r, smem_u32(p));
                    b[2 * np][0] = r[0];     b[2 * np][1] = r[2];
                    b[2 * np + 1][0] = r[1]; b[2 * np + 1][1] = r[3];
                }
                #pragma unroll
                for (int mt = 0; mt < 2; mt++)
                    #pragma unroll
                    for (int nt = 0; nt < 8; nt++)
                        mma_bf16(acc[mt][nt], a[mt], b[nt]);
            }
            __syncthreads();
        }

        const float s = g_sAB;
        const int groupID = lane >> 2, tig = lane & 3;
        #pragma unroll
        for (int mt = 0; mt < 2; mt++) {
            #pragma unroll
            for (int nt = 0; nt < 8; nt++) {
                int row0 = bm + warpM * 32 + mt * 16 + groupID;
                int col  = bnh + warpN * 64 + nt * 8 + tig * 2;
                float2 v0 = make_float2(acc[mt][nt][0] * s, acc[mt][nt][1] * s);
                float2 v1 = make_float2(acc[mt][nt][2] * s, acc[mt][nt][3] * s);
                *(float2*)&C[(size_t)row0 * N_DIM + col]       = v0;
                *(float2*)&C[(size_t)(row0 + 8) * N_DIM + col] = v1;
            }
        }
    }
    #undef LDA_S
#endif
}

// ---------------- launch ----------------
extern "C" void kernel_launch(void* const* d_in, const int* in_sizes, int n_in,
                              void* d_out, int out_size) {
    const float* A = (const float*)d_in[0];  // [4096, 2048]
    const float* B = (const float*)d_in[1];  // [2048, 4096]
    float* C = (float*)d_out;                // [4096, 4096]

    const int nA = M_DIM * K_DIM;

    minmax_fused<<<2 * MMG, 256>>>(A, B);
    finalize_scales<<<1, 256>>>();

    quantize_A<<<(nA / 8 + 255) / 256, 256>>>(A, nA / 8);
    dim3 tgrid(N_DIM / 64, K_DIM / 64);
    quantize_B_T<<<tgrid, 256>>>(B);

    cudaFuncSetAttribute(gemm_tc, cudaFuncAttributeMaxDynamicSharedMemorySize, SMEM_TOTAL);
    dim3 grid(N_DIM / BN, M_DIM / BM);  // 16 x 32
    gemm_tc<<<grid, 256, SMEM_TOTAL>>>(C);
}